// round 14
// baseline (speedup 1.0000x reference)
#include <cuda_runtime.h>
#include <math.h>

#define N_FFT   16000
#define IN_DIM  2048
#define BATCH   512
#define TPB     640          // 16000 / 640 = 25 bins per thread
#define NQ      25
#define NCTA    (BATCH / 2)  // 256 CTAs in cbp_main
#define SMEM_BYTES ((N_FFT + 8000) * (int)sizeof(float2))   // 192000 B (proven)

// ---------------- device scratch (no allocations allowed) ----------------
__device__ int    g_h1[IN_DIM], g_h2[IN_DIM];
__device__ float  g_s1[IN_DIM], g_s2[IN_DIM];
__device__ float  g_part2[NCTA * N_FFT];   // per-CTA column partials of ss^2 (16.4 MB)
__device__ float  g_norminv[N_FFT];
__device__ float2 g_tw[8000];              // twiddle table, computed once
// per-CTA parking for G1 spectrum (256 CTAs x 16000 complex = 32.8 MB, static)
__device__ float2 g_park[NCTA * N_FFT];

// ---------------- complex helpers ----------------
__device__ __forceinline__ float2 cmulf(float2 a, float2 b) {
    return make_float2(fmaf(a.x, b.x, -a.y * b.y), fmaf(a.x, b.y, a.y * b.x));
}
// a * conj(b)
__device__ __forceinline__ float2 cmulcf(float2 a, float2 b) {
    return make_float2(fmaf(a.x, b.x, a.y * b.y), fmaf(a.y, b.x, -a.x * b.y));
}
// W[k] = e^{-2*pi*i*k/16000}, table holds k in [0,8000), W[k+8000] = -W[k]
__device__ __forceinline__ float2 twget(const float2* __restrict__ w, int k) {
    float2 t = w[(k < 8000) ? k : (k - 8000)];
    if (k >= 8000) { t.x = -t.x; t.y = -t.y; }
    return t;
}

// ---- digit maps between digit-reversed position p and frequency bin k ----
// fwd DIF radices 5,5,5,4,4,4,2; strides 3200,640,128,32,8,2,1  (unchanged)
__device__ __forceinline__ int bin_from_pos(int p) {
    int m1 = p / 3200; p -= m1 * 3200;
    int m2 = p / 640;  p -= m2 * 640;
    int m3 = p / 128;  p -= m3 * 128;
    int m4 = p / 32;   p -= m4 * 32;
    int m5 = p / 8;    p -= m5 * 8;
    int m6 = p / 2;    p -= m6 * 2;
    int m7 = p;
    return m1 + 5 * (m2 + 5 * (m3 + 5 * (m4 + 4 * (m5 + 4 * (m6 + 4 * m7)))));
}
__device__ __forceinline__ int pos_from_bin(int k) {
    int m1 = k % 5; k /= 5;
    int m2 = k % 5; k /= 5;
    int m3 = k % 5; k /= 5;
    int m4 = k & 3; k >>= 2;
    int m5 = k & 3; k >>= 2;
    int m6 = k & 3; k >>= 2;
    return m1 * 3200 + m2 * 640 + m3 * 128 + m4 * 32 + m5 * 8 + m6 * 2 + k;
}

// ---------------- register-level radix butterflies ----------------
__device__ __forceinline__ void r5_fwd(float2* a, const float2* __restrict__ w, int kk) {
    float2 t1 = {a[1].x + a[4].x, a[1].y + a[4].y};
    float2 t2 = {a[2].x + a[3].x, a[2].y + a[3].y};
    float2 t3 = {a[1].x - a[4].x, a[1].y - a[4].y};
    float2 t4 = {a[2].x - a[3].x, a[2].y - a[3].y};
    float2 X0 = {a[0].x + t1.x + t2.x, a[0].y + t1.y + t2.y};
    const float C1 = 0.30901699437494742f, C2 = -0.80901699437494742f;
    const float S1 = 0.95105651629515357f, S2 =  0.58778525229247312f;
    float2 m1 = {C1 * t1.x + C2 * t2.x, C1 * t1.y + C2 * t2.y};
    float2 m2 = {C2 * t1.x + C1 * t2.x, C2 * t1.y + C1 * t2.y};
    float2 m3 = {S1 * t3.x + S2 * t4.x, S1 * t3.y + S2 * t4.y};
    float2 m4 = {S2 * t3.x - S1 * t4.x, S2 * t3.y - S1 * t4.y};
    float2 y1 = {a[0].x + m1.x, a[0].y + m1.y};
    float2 y2 = {a[0].x + m2.x, a[0].y + m2.y};
    float2 X1 = {y1.x + m3.y, y1.y - m3.x};   // y1 - i*m3
    float2 X4 = {y1.x - m3.y, y1.y + m3.x};
    float2 X2 = {y2.x + m4.y, y2.y - m4.x};
    float2 X3 = {y2.x - m4.y, y2.y + m4.x};
    a[0] = X0;
    a[1] = cmulf(X1, twget(w, kk));
    a[2] = cmulf(X2, twget(w, 2 * kk));
    a[3] = cmulf(X3, twget(w, 3 * kk));
    a[4] = cmulf(X4, twget(w, 4 * kk));
}
__device__ __forceinline__ void r5_inv(float2* a, const float2* __restrict__ w, int kk) {
    a[1] = cmulcf(a[1], twget(w, kk));
    a[2] = cmulcf(a[2], twget(w, 2 * kk));
    a[3] = cmulcf(a[3], twget(w, 3 * kk));
    a[4] = cmulcf(a[4], twget(w, 4 * kk));
    float2 t1 = {a[1].x + a[4].x, a[1].y + a[4].y};
    float2 t2 = {a[2].x + a[3].x, a[2].y + a[3].y};
    float2 t3 = {a[1].x - a[4].x, a[1].y - a[4].y};
    float2 t4 = {a[2].x - a[3].x, a[2].y - a[3].y};
    float2 X0 = {a[0].x + t1.x + t2.x, a[0].y + t1.y + t2.y};
    const float C1 = 0.30901699437494742f, C2 = -0.80901699437494742f;
    const float S1 = 0.95105651629515357f, S2 =  0.58778525229247312f;
    float2 m1 = {C1 * t1.x + C2 * t2.x, C1 * t1.y + C2 * t2.y};
    float2 m2 = {C2 * t1.x + C1 * t2.x, C2 * t1.y + C1 * t2.y};
    float2 m3 = {S1 * t3.x + S2 * t4.x, S1 * t3.y + S2 * t4.y};
    float2 m4 = {S2 * t3.x - S1 * t4.x, S2 * t3.y - S1 * t4.y};
    float2 y1 = {a[0].x + m1.x, a[0].y + m1.y};
    float2 y2 = {a[0].x + m2.x, a[0].y + m2.y};
    a[0] = X0;
    a[1] = {y1.x - m3.y, y1.y + m3.x};        // y1 + i*m3
    a[4] = {y1.x + m3.y, y1.y - m3.x};
    a[2] = {y2.x - m4.y, y2.y + m4.x};
    a[3] = {y2.x + m4.y, y2.y - m4.x};
}
__device__ __forceinline__ void r4_fwd(float2* a, const float2* __restrict__ w, int kk) {
    float2 t0 = {a[0].x + a[2].x, a[0].y + a[2].y};
    float2 t1 = {a[0].x - a[2].x, a[0].y - a[2].y};
    float2 t2 = {a[1].x + a[3].x, a[1].y + a[3].y};
    float2 t3 = {a[1].x - a[3].x, a[1].y - a[3].y};
    float2 X0 = {t0.x + t2.x, t0.y + t2.y};
    float2 X2 = {t0.x - t2.x, t0.y - t2.y};
    float2 X1 = {t1.x + t3.y, t1.y - t3.x};   // t1 - i*t3
    float2 X3 = {t1.x - t3.y, t1.y + t3.x};
    a[0] = X0;
    a[1] = cmulf(X1, twget(w, kk));
    a[2] = cmulf(X2, twget(w, 2 * kk));
    a[3] = cmulf(X3, twget(w, 3 * kk));
}
__device__ __forceinline__ void r4_inv(float2* a, const float2* __restrict__ w, int kk) {
    a[1] = cmulcf(a[1], twget(w, kk));
    a[2] = cmulcf(a[2], twget(w, 2 * kk));
    a[3] = cmulcf(a[3], twget(w, 3 * kk));
    float2 t0 = {a[0].x + a[2].x, a[0].y + a[2].y};
    float2 t1 = {a[0].x - a[2].x, a[0].y - a[2].y};
    float2 t2 = {a[1].x + a[3].x, a[1].y + a[3].y};
    float2 t3 = {a[1].x - a[3].x, a[1].y - a[3].y};
    a[0] = {t0.x + t2.x, t0.y + t2.y};
    a[2] = {t0.x - t2.x, t0.y - t2.y};
    a[1] = {t1.x - t3.y, t1.y + t3.x};        // t1 + i*t3
    a[3] = {t1.x + t3.y, t1.y - t3.x};
}

// ---------------- merged phases (unpadded layout, conflict-free lanes) ----------------
// phaseA: L=16000 (r5, stride 3200, step 1) + L=3200 (r5, stride 640, step 5)
__device__ __forceinline__ void phaseA_fwd(float2* buf, const float2* w, int tid) {
    float2 x[5][5];   // x[r][s] at position tid + 640*s + 3200*r
    #pragma unroll
    for (int r = 0; r < 5; ++r)
        #pragma unroll
        for (int s = 0; s < 5; ++s)
            x[r][s] = buf[tid + 640 * s + 3200 * r];
    #pragma unroll
    for (int s = 0; s < 5; ++s) {
        float2 c[5] = {x[0][s], x[1][s], x[2][s], x[3][s], x[4][s]};
        r5_fwd(c, w, tid + 640 * s);
        x[0][s] = c[0]; x[1][s] = c[1]; x[2][s] = c[2]; x[3][s] = c[3]; x[4][s] = c[4];
    }
    #pragma unroll
    for (int r = 0; r < 5; ++r) r5_fwd(x[r], w, 5 * tid);
    #pragma unroll
    for (int r = 0; r < 5; ++r)
        #pragma unroll
        for (int s = 0; s < 5; ++s)
            buf[tid + 640 * s + 3200 * r] = x[r][s];
    __syncthreads();
}
__device__ __forceinline__ void phaseA_inv(float2* buf, const float2* w, int tid) {
    float2 x[5][5];
    #pragma unroll
    for (int r = 0; r < 5; ++r)
        #pragma unroll
        for (int s = 0; s < 5; ++s)
            x[r][s] = buf[tid + 640 * s + 3200 * r];
    #pragma unroll
    for (int r = 0; r < 5; ++r) r5_inv(x[r], w, 5 * tid);
    #pragma unroll
    for (int s = 0; s < 5; ++s) {
        float2 c[5] = {x[0][s], x[1][s], x[2][s], x[3][s], x[4][s]};
        r5_inv(c, w, tid + 640 * s);
        x[0][s] = c[0]; x[1][s] = c[1]; x[2][s] = c[2]; x[3][s] = c[3]; x[4][s] = c[4];
    }
    #pragma unroll
    for (int r = 0; r < 5; ++r)
        #pragma unroll
        for (int s = 0; s < 5; ++s)
            buf[tid + 640 * s + 3200 * r] = x[r][s];
    __syncthreads();
}
// phaseB: L=640 (r5, stride 128, step 25) + L=128 (r4, stride 32, step 125)
__device__ __forceinline__ void phaseB_fwd(float2* buf, const float2* w, int tid) {
    for (int g = tid; g < 800; g += TPB) {
        int b = g >> 5, jp = g & 31;
        int base = 640 * b + jp;
        float2 x[5][4];   // x[r][q] at base + 128*r + 32*q
        #pragma unroll
        for (int r = 0; r < 5; ++r)
            #pragma unroll
            for (int q = 0; q < 4; ++q)
                x[r][q] = buf[base + 128 * r + 32 * q];
        #pragma unroll
        for (int q = 0; q < 4; ++q) {
            float2 c[5] = {x[0][q], x[1][q], x[2][q], x[3][q], x[4][q]};
            r5_fwd(c, w, 25 * (jp + 32 * q));
            x[0][q] = c[0]; x[1][q] = c[1]; x[2][q] = c[2]; x[3][q] = c[3]; x[4][q] = c[4];
        }
        #pragma unroll
        for (int r = 0; r < 5; ++r) r4_fwd(x[r], w, 125 * jp);
        #pragma unroll
        for (int r = 0; r < 5; ++r)
            #pragma unroll
            for (int q = 0; q < 4; ++q)
                buf[base + 128 * r + 32 * q] = x[r][q];
    }
    __syncthreads();
}
__device__ __forceinline__ void phaseB_inv(float2* buf, const float2* w, int tid) {
    for (int g = tid; g < 800; g += TPB) {
        int b = g >> 5, jp = g & 31;
        int base = 640 * b + jp;
        float2 x[5][4];
        #pragma unroll
        for (int r = 0; r < 5; ++r)
            #pragma unroll
            for (int q = 0; q < 4; ++q)
                x[r][q] = buf[base + 128 * r + 32 * q];
        #pragma unroll
        for (int r = 0; r < 5; ++r) r4_inv(x[r], w, 125 * jp);
        #pragma unroll
        for (int q = 0; q < 4; ++q) {
            float2 c[5] = {x[0][q], x[1][q], x[2][q], x[3][q], x[4][q]};
            r5_inv(c, w, 25 * (jp + 32 * q));
            x[0][q] = c[0]; x[1][q] = c[1]; x[2][q] = c[2]; x[3][q] = c[3]; x[4][q] = c[4];
        }
        #pragma unroll
        for (int r = 0; r < 5; ++r)
            #pragma unroll
            for (int q = 0; q < 4; ++q)
                buf[base + 128 * r + 32 * q] = x[r][q];
    }
    __syncthreads();
}

// ---------------- tail stages (unpadded, low register pressure) ----------------
template<bool INV>
__device__ __forceinline__ void stage4(float2* buf, const float2* w, int L, int tid) {
    const int M = L / 4;
    const int step = N_FFT / L;
    for (int t = tid; t < N_FFT / 4; t += TPB) {
        int blk = t / M;
        int j   = t - blk * M;
        int o   = blk * L + j;
        float2 a[4] = {buf[o], buf[o + M], buf[o + 2 * M], buf[o + 3 * M]};
        if (!INV) r4_fwd(a, w, step * j);
        else      r4_inv(a, w, step * j);
        buf[o]         = a[0];
        buf[o + M]     = a[1];
        buf[o + 2 * M] = a[2];
        buf[o + 3 * M] = a[3];
    }
    __syncthreads();
}
template<bool INV>
__device__ __forceinline__ void stage2(float2* buf, const float2* w, int tid) {
    // L = 2, M = 1, step = 8000; twiddle W^{8000*0} = 1 -> twiddle-free
    for (int t = tid; t < N_FFT / 2; t += TPB) {
        int o = 2 * t;
        float2 a = buf[o];
        float2 b = buf[o + 1];
        buf[o]     = {a.x + b.x, a.y + b.y};
        buf[o + 1] = {a.x - b.x, a.y - b.y};
    }
    __syncthreads();
}

__device__ __forceinline__ void fft16000(float2* buf, const float2* w, int tid, bool inv) {
    if (!inv) {
        phaseA_fwd(buf, w, tid);
        phaseB_fwd(buf, w, tid);
        stage4<false>(buf, w, 32, tid);
        stage4<false>(buf, w, 8,  tid);
        stage2<false>(buf, w, tid);
    } else {
        stage2<true>(buf, w, tid);
        stage4<true>(buf, w, 8,  tid);
        stage4<true>(buf, w, 32, tid);
        phaseB_inv(buf, w, tid);
        phaseA_inv(buf, w, tid);
    }
}

// scatter one batch row of x1 into .x and x2 into .y -> z = p1 + i*p2
__device__ __forceinline__ void scatter_row(float2* buf,
                                            const float* __restrict__ x1,
                                            const float* __restrict__ x2,
                                            int b, int tid) {
    for (int k = tid; k < N_FFT; k += TPB) buf[k] = make_float2(0.f, 0.f);
    __syncthreads();
    for (int i = tid; i < IN_DIM; i += TPB) {
        atomicAdd(&buf[g_h1[i]].x, x1[(size_t)b * IN_DIM + i] * g_s1[i]);
        atomicAdd(&buf[g_h2[i]].y, x2[(size_t)b * IN_DIM + i] * g_s2[i]);
    }
    __syncthreads();
}

// buf holds Z = FFT(p1 + i*p2) digit-reversed; replace with G = F1*F2
// G = -i/4 * (Z(k)^2 - conj(Z(N-k))^2), G(N-k) = conj(G(k)); pair-owner scheme.
__device__ __forceinline__ void spectral_product(float2* buf, int tid) {
    #pragma unroll
    for (int q = 0; q < NQ; ++q) {
        int p = tid + q * TPB;
        int k = bin_from_pos(p);
        int kc = k ? (N_FFT - k) : 0;
        int pp = pos_from_bin(kc);
        if (pp < p) continue;
        float2 zp = buf[p];
        float2 zq = buf[pp];
        float2 a  = {fmaf(zp.x, zp.x, -zp.y * zp.y), 2.f * zp.x * zp.y};
        float2 bb = {fmaf(zq.x, zq.x, -zq.y * zq.y), -2.f * zq.x * zq.y};
        float2 d  = {a.x - bb.x, a.y - bb.y};
        float2 G  = {0.25f * d.y, -0.25f * d.x};
        buf[p]  = G;
        buf[pp] = make_float2(G.x, -G.y);
    }
    __syncthreads();
}

// ---------------- kernel 0: one-time twiddle table ----------------
__global__ void cbp_twiddles() {
    int k = blockIdx.x * blockDim.x + threadIdx.x;
    if (k >= 8000) return;
    const float wstep = -6.283185307179586477f / (float)N_FFT;
    float sn, cs;
    sincosf(wstep * (float)k, &sn, &cs);
    g_tw[k] = make_float2(cs, sn);
}

// ---------------- kernel 1: extract count-sketch (h, s) ----------------
__global__ void cbp_extract(const float* __restrict__ sk1, const float* __restrict__ sk2) {
    int gt   = blockIdx.x * blockDim.x + threadIdx.x;
    int warp = gt >> 5;
    int lane = gt & 31;
    if (warp >= 2 * IN_DIM) return;
    const float* sk;
    int row;
    int*   H;
    float* S;
    if (warp < IN_DIM) { sk = sk1; row = warp;          H = g_h1; S = g_s1; }
    else               { sk = sk2; row = warp - IN_DIM; H = g_h2; S = g_s2; }
    const float4* p = (const float4*)(sk + (size_t)row * N_FFT);
    #pragma unroll 4
    for (int it = 0; it < N_FFT / 128; ++it) {          // 125 iterations
        int idx4 = it * 32 + lane;
        float4 v = p[idx4];
        int base = idx4 * 4;
        if (v.x != 0.f) { H[row] = base;     S[row] = v.x; }
        if (v.y != 0.f) { H[row] = base + 1; S[row] = v.y; }
        if (v.z != 0.f) { H[row] = base + 2; S[row] = v.z; }
        if (v.w != 0.f) { H[row] = base + 3; S[row] = v.w; }
    }
}

// ---------------- kernel 2: TWO batch rows per CTA + fused colsum partial ----------------
__global__ __launch_bounds__(TPB, 1)
void cbp_main(const float* __restrict__ x1, const float* __restrict__ x2,
              float* __restrict__ out) {
    extern __shared__ __align__(16) unsigned char smraw[];
    float2* buf = (float2*)smraw;                              // 16000 complex
    float2* w   = (float2*)(smraw + N_FFT * sizeof(float2));   // 8000 twiddles
    const int tid = threadIdx.x;
    const int b0  = 2 * blockIdx.x;
    float2* park = g_park + (size_t)blockIdx.x * N_FFT;
    float*  part = g_part2 + (size_t)blockIdx.x * N_FFT;

    // load twiddle table from global (coalesced, L2-resident after wave 1)
    for (int k = tid; k < 8000; k += TPB) w[k] = g_tw[k];

    // ---- row b0 ----
    scatter_row(buf, x1, x2, b0, tid);
    fft16000(buf, w, tid, false);
    spectral_product(buf, tid);
    #pragma unroll
    for (int q = 0; q < NQ; ++q) {          // park G_b0
        int p = tid + q * TPB;
        park[p] = buf[p];
    }
    // per-thread index sets of park-read/zero-write coincide -> no sync needed

    // ---- row b0+1 ----
    scatter_row(buf, x1, x2, b0 + 1, tid);
    fft16000(buf, w, tid, false);
    spectral_product(buf, tid);

    // combine: buf = G_b0 + i * G_{b0+1}
    #pragma unroll
    for (int q = 0; q < NQ; ++q) {
        int p = tid + q * TPB;
        float2 g1 = park[p];
        float2 g2 = buf[p];
        buf[p] = make_float2(g1.x - g2.y, g1.y + g2.x);
    }
    __syncthreads();

    fft16000(buf, w, tid, true);            // unnormalized inverse = N * cbp

    // signed sqrt + per-column ss^2 partial (ss^2 = |cbp| exactly)
    for (int k = tid; k < N_FFT; k += TPB) {
        float2 c = buf[k];
        out[(size_t)b0 * N_FFT + k]       = copysignf(sqrtf(fabsf(c.x)), c.x);
        out[(size_t)(b0 + 1) * N_FFT + k] = copysignf(sqrtf(fabsf(c.y)), c.y);
        part[k] = fabsf(c.x) + fabsf(c.y);
    }
}

// ---------------- kernel 3: finalize column norms (reduce 256 partials) ----------------
__global__ void cbp_colsum_final() {
    int k = blockIdx.x * blockDim.x + threadIdx.x;
    if (k >= N_FFT) return;
    float acc = 0.f;
    #pragma unroll 8
    for (int c = 0; c < NCTA; ++c) acc += g_part2[(size_t)c * N_FFT + k];
    g_norminv[k] = 1.f / fmaxf(sqrtf(acc), 1e-12f);
}

// ---------------- kernel 4: scale output columns ----------------
__global__ void cbp_norm(float* __restrict__ out) {
    int i = blockIdx.x * blockDim.x + threadIdx.x;
    if (i >= BATCH * N_FFT / 4) return;
    int e = i * 4;
    int k = e % N_FFT;
    float4 v = ((float4*)out)[i];
    v.x *= g_norminv[k];
    v.y *= g_norminv[k + 1];
    v.z *= g_norminv[k + 2];
    v.w *= g_norminv[k + 3];
    ((float4*)out)[i] = v;
}

// ---------------- launch ----------------
extern "C" void kernel_launch(void* const* d_in, const int* in_sizes, int n_in,
                              void* d_out, int out_size) {
    const float* xs[2]  = {nullptr, nullptr};
    const float* sks[2] = {nullptr, nullptr};
    int nx = 0, ns = 0;
    for (int i = 0; i < n_in; ++i) {
        if (in_sizes[i] == BATCH * IN_DIM && nx < 2)       xs[nx++]  = (const float*)d_in[i];
        else if (in_sizes[i] == IN_DIM * N_FFT && ns < 2)  sks[ns++] = (const float*)d_in[i];
    }
    float* out = (float*)d_out;

    cudaFuncSetAttribute(cbp_main, cudaFuncAttributeMaxDynamicSharedMemorySize, SMEM_BYTES);

    cbp_twiddles<<<(8000 + 255) / 256, 256>>>();
    cbp_extract<<<(2 * IN_DIM * 32 + 255) / 256, 256>>>(sks[0], sks[1]);
    cbp_main<<<NCTA, TPB, SMEM_BYTES>>>(xs[0], xs[1], out);
    cbp_colsum_final<<<(N_FFT + 127) / 128, 128>>>();
    cbp_norm<<<(BATCH * N_FFT / 4 + 255) / 256, 256>>>(out);
}

// round 16
// speedup vs baseline: 1.1175x; 1.1175x over previous
#include <cuda_runtime.h>
#include <math.h>

#define N_FFT   16000
#define IN_DIM  2048
#define BATCH   512
#define TPB     640          // 16000 / 640 = 25 bins per thread
#define NQ      25
#define NCTA    (BATCH / 2)  // 256 CTAs in cbp_main
#define SMEM_BYTES ((N_FFT + 8000) * (int)sizeof(float2))   // 192000 B (proven)

// ---------------- device scratch (no allocations allowed) ----------------
__device__ int    g_h1[IN_DIM], g_h2[IN_DIM];
__device__ float  g_s1[IN_DIM], g_s2[IN_DIM];
__device__ float  g_part2[NCTA * N_FFT];   // per-CTA column partials of ss^2 (16.4 MB)
__device__ float  g_norminv[N_FFT];
// per-CTA parking for G1 spectrum (256 CTAs x 16000 complex = 32.8 MB, static)
__device__ float2 g_park[NCTA * N_FFT];

// ---------------- complex helpers ----------------
__device__ __forceinline__ float2 cmulf(float2 a, float2 b) {
    return make_float2(fmaf(a.x, b.x, -a.y * b.y), fmaf(a.x, b.y, a.y * b.x));
}
// a * conj(b)
__device__ __forceinline__ float2 cmulcf(float2 a, float2 b) {
    return make_float2(fmaf(a.x, b.x, a.y * b.y), fmaf(a.y, b.x, -a.x * b.y));
}
// W[k] = e^{-2*pi*i*k/16000}, table holds k in [0,8000), W[k+8000] = -W[k]
__device__ __forceinline__ float2 twget(const float2* __restrict__ w, int k) {
    float2 t = w[(k < 8000) ? k : (k - 8000)];
    if (k >= 8000) { t.x = -t.x; t.y = -t.y; }
    return t;
}

// ---- digit maps between digit-reversed position p and frequency bin k ----
// fwd DIF radices 5,5,5,4,4,4,2; strides 3200,640,128,32,8,2,1  (unchanged)
__device__ __forceinline__ int bin_from_pos(int p) {
    int m1 = p / 3200; p -= m1 * 3200;
    int m2 = p / 640;  p -= m2 * 640;
    int m3 = p / 128;  p -= m3 * 128;
    int m4 = p / 32;   p -= m4 * 32;
    int m5 = p / 8;    p -= m5 * 8;
    int m6 = p / 2;    p -= m6 * 2;
    int m7 = p;
    return m1 + 5 * (m2 + 5 * (m3 + 5 * (m4 + 4 * (m5 + 4 * (m6 + 4 * m7)))));
}
__device__ __forceinline__ int pos_from_bin(int k) {
    int m1 = k % 5; k /= 5;
    int m2 = k % 5; k /= 5;
    int m3 = k % 5; k /= 5;
    int m4 = k & 3; k >>= 2;
    int m5 = k & 3; k >>= 2;
    int m6 = k & 3; k >>= 2;
    return m1 * 3200 + m2 * 640 + m3 * 128 + m4 * 32 + m5 * 8 + m6 * 2 + k;
}

// ---------------- register-level radix butterflies ----------------
__device__ __forceinline__ void r5_fwd(float2* a, const float2* __restrict__ w, int kk) {
    float2 t1 = {a[1].x + a[4].x, a[1].y + a[4].y};
    float2 t2 = {a[2].x + a[3].x, a[2].y + a[3].y};
    float2 t3 = {a[1].x - a[4].x, a[1].y - a[4].y};
    float2 t4 = {a[2].x - a[3].x, a[2].y - a[3].y};
    float2 X0 = {a[0].x + t1.x + t2.x, a[0].y + t1.y + t2.y};
    const float C1 = 0.30901699437494742f, C2 = -0.80901699437494742f;
    const float S1 = 0.95105651629515357f, S2 =  0.58778525229247312f;
    float2 m1 = {C1 * t1.x + C2 * t2.x, C1 * t1.y + C2 * t2.y};
    float2 m2 = {C2 * t1.x + C1 * t2.x, C2 * t1.y + C1 * t2.y};
    float2 m3 = {S1 * t3.x + S2 * t4.x, S1 * t3.y + S2 * t4.y};
    float2 m4 = {S2 * t3.x - S1 * t4.x, S2 * t3.y - S1 * t4.y};
    float2 y1 = {a[0].x + m1.x, a[0].y + m1.y};
    float2 y2 = {a[0].x + m2.x, a[0].y + m2.y};
    float2 X1 = {y1.x + m3.y, y1.y - m3.x};   // y1 - i*m3
    float2 X4 = {y1.x - m3.y, y1.y + m3.x};
    float2 X2 = {y2.x + m4.y, y2.y - m4.x};
    float2 X3 = {y2.x - m4.y, y2.y + m4.x};
    a[0] = X0;
    a[1] = cmulf(X1, twget(w, kk));
    a[2] = cmulf(X2, twget(w, 2 * kk));
    a[3] = cmulf(X3, twget(w, 3 * kk));
    a[4] = cmulf(X4, twget(w, 4 * kk));
}
__device__ __forceinline__ void r5_inv(float2* a, const float2* __restrict__ w, int kk) {
    a[1] = cmulcf(a[1], twget(w, kk));
    a[2] = cmulcf(a[2], twget(w, 2 * kk));
    a[3] = cmulcf(a[3], twget(w, 3 * kk));
    a[4] = cmulcf(a[4], twget(w, 4 * kk));
    float2 t1 = {a[1].x + a[4].x, a[1].y + a[4].y};
    float2 t2 = {a[2].x + a[3].x, a[2].y + a[3].y};
    float2 t3 = {a[1].x - a[4].x, a[1].y - a[4].y};
    float2 t4 = {a[2].x - a[3].x, a[2].y - a[3].y};
    float2 X0 = {a[0].x + t1.x + t2.x, a[0].y + t1.y + t2.y};
    const float C1 = 0.30901699437494742f, C2 = -0.80901699437494742f;
    const float S1 = 0.95105651629515357f, S2 =  0.58778525229247312f;
    float2 m1 = {C1 * t1.x + C2 * t2.x, C1 * t1.y + C2 * t2.y};
    float2 m2 = {C2 * t1.x + C1 * t2.x, C2 * t1.y + C1 * t2.y};
    float2 m3 = {S1 * t3.x + S2 * t4.x, S1 * t3.y + S2 * t4.y};
    float2 m4 = {S2 * t3.x - S1 * t4.x, S2 * t3.y - S1 * t4.y};
    float2 y1 = {a[0].x + m1.x, a[0].y + m1.y};
    float2 y2 = {a[0].x + m2.x, a[0].y + m2.y};
    a[0] = X0;
    a[1] = {y1.x - m3.y, y1.y + m3.x};        // y1 + i*m3
    a[4] = {y1.x + m3.y, y1.y - m3.x};
    a[2] = {y2.x - m4.y, y2.y + m4.x};
    a[3] = {y2.x + m4.y, y2.y - m4.x};
}
__device__ __forceinline__ void r4_fwd(float2* a, const float2* __restrict__ w, int kk) {
    float2 t0 = {a[0].x + a[2].x, a[0].y + a[2].y};
    float2 t1 = {a[0].x - a[2].x, a[0].y - a[2].y};
    float2 t2 = {a[1].x + a[3].x, a[1].y + a[3].y};
    float2 t3 = {a[1].x - a[3].x, a[1].y - a[3].y};
    float2 X0 = {t0.x + t2.x, t0.y + t2.y};
    float2 X2 = {t0.x - t2.x, t0.y - t2.y};
    float2 X1 = {t1.x + t3.y, t1.y - t3.x};   // t1 - i*t3
    float2 X3 = {t1.x - t3.y, t1.y + t3.x};
    a[0] = X0;
    a[1] = cmulf(X1, twget(w, kk));
    a[2] = cmulf(X2, twget(w, 2 * kk));
    a[3] = cmulf(X3, twget(w, 3 * kk));
}
__device__ __forceinline__ void r4_inv(float2* a, const float2* __restrict__ w, int kk) {
    a[1] = cmulcf(a[1], twget(w, kk));
    a[2] = cmulcf(a[2], twget(w, 2 * kk));
    a[3] = cmulcf(a[3], twget(w, 3 * kk));
    float2 t0 = {a[0].x + a[2].x, a[0].y + a[2].y};
    float2 t1 = {a[0].x - a[2].x, a[0].y - a[2].y};
    float2 t2 = {a[1].x + a[3].x, a[1].y + a[3].y};
    float2 t3 = {a[1].x - a[3].x, a[1].y - a[3].y};
    a[0] = {t0.x + t2.x, t0.y + t2.y};
    a[2] = {t0.x - t2.x, t0.y - t2.y};
    a[1] = {t1.x - t3.y, t1.y + t3.x};        // t1 + i*t3
    a[3] = {t1.x + t3.y, t1.y - t3.x};
}

// ---------------- merged phases (unpadded layout, conflict-free lanes) ----------------
// phaseA: L=16000 (r5, stride 3200, step 1) + L=3200 (r5, stride 640, step 5)
__device__ __forceinline__ void phaseA_fwd(float2* buf, const float2* w, int tid) {
    float2 x[5][5];   // x[r][s] at position tid + 640*s + 3200*r
    #pragma unroll
    for (int r = 0; r < 5; ++r)
        #pragma unroll
        for (int s = 0; s < 5; ++s)
            x[r][s] = buf[tid + 640 * s + 3200 * r];
    #pragma unroll
    for (int s = 0; s < 5; ++s) {
        float2 c[5] = {x[0][s], x[1][s], x[2][s], x[3][s], x[4][s]};
        r5_fwd(c, w, tid + 640 * s);
        x[0][s] = c[0]; x[1][s] = c[1]; x[2][s] = c[2]; x[3][s] = c[3]; x[4][s] = c[4];
    }
    #pragma unroll
    for (int r = 0; r < 5; ++r) r5_fwd(x[r], w, 5 * tid);
    #pragma unroll
    for (int r = 0; r < 5; ++r)
        #pragma unroll
        for (int s = 0; s < 5; ++s)
            buf[tid + 640 * s + 3200 * r] = x[r][s];
    __syncthreads();
}
__device__ __forceinline__ void phaseA_inv(float2* buf, const float2* w, int tid) {
    float2 x[5][5];
    #pragma unroll
    for (int r = 0; r < 5; ++r)
        #pragma unroll
        for (int s = 0; s < 5; ++s)
            x[r][s] = buf[tid + 640 * s + 3200 * r];
    #pragma unroll
    for (int r = 0; r < 5; ++r) r5_inv(x[r], w, 5 * tid);
    #pragma unroll
    for (int s = 0; s < 5; ++s) {
        float2 c[5] = {x[0][s], x[1][s], x[2][s], x[3][s], x[4][s]};
        r5_inv(c, w, tid + 640 * s);
        x[0][s] = c[0]; x[1][s] = c[1]; x[2][s] = c[2]; x[3][s] = c[3]; x[4][s] = c[4];
    }
    #pragma unroll
    for (int r = 0; r < 5; ++r)
        #pragma unroll
        for (int s = 0; s < 5; ++s)
            buf[tid + 640 * s + 3200 * r] = x[r][s];
    __syncthreads();
}
// phaseB: L=640 (r5, stride 128, step 25) + L=128 (r4, stride 32, step 125)
__device__ __forceinline__ void phaseB_fwd(float2* buf, const float2* w, int tid) {
    for (int g = tid; g < 800; g += TPB) {
        int b = g >> 5, jp = g & 31;
        int base = 640 * b + jp;
        float2 x[5][4];   // x[r][q] at base + 128*r + 32*q
        #pragma unroll
        for (int r = 0; r < 5; ++r)
            #pragma unroll
            for (int q = 0; q < 4; ++q)
                x[r][q] = buf[base + 128 * r + 32 * q];
        #pragma unroll
        for (int q = 0; q < 4; ++q) {
            float2 c[5] = {x[0][q], x[1][q], x[2][q], x[3][q], x[4][q]};
            r5_fwd(c, w, 25 * (jp + 32 * q));
            x[0][q] = c[0]; x[1][q] = c[1]; x[2][q] = c[2]; x[3][q] = c[3]; x[4][q] = c[4];
        }
        #pragma unroll
        for (int r = 0; r < 5; ++r) r4_fwd(x[r], w, 125 * jp);
        #pragma unroll
        for (int r = 0; r < 5; ++r)
            #pragma unroll
            for (int q = 0; q < 4; ++q)
                buf[base + 128 * r + 32 * q] = x[r][q];
    }
    __syncthreads();
}
__device__ __forceinline__ void phaseB_inv(float2* buf, const float2* w, int tid) {
    for (int g = tid; g < 800; g += TPB) {
        int b = g >> 5, jp = g & 31;
        int base = 640 * b + jp;
        float2 x[5][4];
        #pragma unroll
        for (int r = 0; r < 5; ++r)
            #pragma unroll
            for (int q = 0; q < 4; ++q)
                x[r][q] = buf[base + 128 * r + 32 * q];
        #pragma unroll
        for (int r = 0; r < 5; ++r) r4_inv(x[r], w, 125 * jp);
        #pragma unroll
        for (int q = 0; q < 4; ++q) {
            float2 c[5] = {x[0][q], x[1][q], x[2][q], x[3][q], x[4][q]};
            r5_inv(c, w, 25 * (jp + 32 * q));
            x[0][q] = c[0]; x[1][q] = c[1]; x[2][q] = c[2]; x[3][q] = c[3]; x[4][q] = c[4];
        }
        #pragma unroll
        for (int r = 0; r < 5; ++r)
            #pragma unroll
            for (int q = 0; q < 4; ++q)
                buf[base + 128 * r + 32 * q] = x[r][q];
    }
    __syncthreads();
}

// ---------------- tail stages (unpadded, low register pressure) ----------------
template<bool INV>
__device__ __forceinline__ void stage4(float2* buf, const float2* w, int L, int tid) {
    const int M = L / 4;
    const int step = N_FFT / L;
    for (int t = tid; t < N_FFT / 4; t += TPB) {
        int blk = t / M;
        int j   = t - blk * M;
        int o   = blk * L + j;
        float2 a[4] = {buf[o], buf[o + M], buf[o + 2 * M], buf[o + 3 * M]};
        if (!INV) r4_fwd(a, w, step * j);
        else      r4_inv(a, w, step * j);
        buf[o]         = a[0];
        buf[o + M]     = a[1];
        buf[o + 2 * M] = a[2];
        buf[o + 3 * M] = a[3];
    }
    __syncthreads();
}
template<bool INV>
__device__ __forceinline__ void stage2(float2* buf, const float2* w, int tid) {
    // L = 2, M = 1, step = 8000; twiddle W^{8000*0} = 1 -> twiddle-free
    for (int t = tid; t < N_FFT / 2; t += TPB) {
        int o = 2 * t;
        float2 a = buf[o];
        float2 b = buf[o + 1];
        buf[o]     = {a.x + b.x, a.y + b.y};
        buf[o + 1] = {a.x - b.x, a.y - b.y};
    }
    __syncthreads();
}

__device__ __forceinline__ void fft16000(float2* buf, const float2* w, int tid, bool inv) {
    if (!inv) {
        phaseA_fwd(buf, w, tid);
        phaseB_fwd(buf, w, tid);
        stage4<false>(buf, w, 32, tid);
        stage4<false>(buf, w, 8,  tid);
        stage2<false>(buf, w, tid);
    } else {
        stage2<true>(buf, w, tid);
        stage4<true>(buf, w, 8,  tid);
        stage4<true>(buf, w, 32, tid);
        phaseB_inv(buf, w, tid);
        phaseA_inv(buf, w, tid);
    }
}

// scatter one batch row of x1 into .x and x2 into .y -> z = p1 + i*p2
__device__ __forceinline__ void scatter_row(float2* buf,
                                            const float* __restrict__ x1,
                                            const float* __restrict__ x2,
                                            int b, int tid) {
    for (int k = tid; k < N_FFT; k += TPB) buf[k] = make_float2(0.f, 0.f);
    __syncthreads();
    for (int i = tid; i < IN_DIM; i += TPB) {
        atomicAdd(&buf[g_h1[i]].x, x1[(size_t)b * IN_DIM + i] * g_s1[i]);
        atomicAdd(&buf[g_h2[i]].y, x2[(size_t)b * IN_DIM + i] * g_s2[i]);
    }
    __syncthreads();
}

// buf holds Z = FFT(p1 + i*p2) digit-reversed; replace with G = F1*F2
// G = -i/4 * (Z(k)^2 - conj(Z(N-k))^2), G(N-k) = conj(G(k)); pair-owner scheme.
__device__ __forceinline__ void spectral_product(float2* buf, int tid) {
    #pragma unroll
    for (int q = 0; q < NQ; ++q) {
        int p = tid + q * TPB;
        int k = bin_from_pos(p);
        int kc = k ? (N_FFT - k) : 0;
        int pp = pos_from_bin(kc);
        if (pp < p) continue;
        float2 zp = buf[p];
        float2 zq = buf[pp];
        float2 a  = {fmaf(zp.x, zp.x, -zp.y * zp.y), 2.f * zp.x * zp.y};
        float2 bb = {fmaf(zq.x, zq.x, -zq.y * zq.y), -2.f * zq.x * zq.y};
        float2 d  = {a.x - bb.x, a.y - bb.y};
        float2 G  = {0.25f * d.y, -0.25f * d.x};
        buf[p]  = G;
        buf[pp] = make_float2(G.x, -G.y);
    }
    __syncthreads();
}

// ---------------- kernel 1: extract count-sketch (h, s) ----------------
__global__ void cbp_extract(const float* __restrict__ sk1, const float* __restrict__ sk2) {
    int gt   = blockIdx.x * blockDim.x + threadIdx.x;
    int warp = gt >> 5;
    int lane = gt & 31;
    if (warp >= 2 * IN_DIM) return;
    const float* sk;
    int row;
    int*   H;
    float* S;
    if (warp < IN_DIM) { sk = sk1; row = warp;          H = g_h1; S = g_s1; }
    else               { sk = sk2; row = warp - IN_DIM; H = g_h2; S = g_s2; }
    const float4* p = (const float4*)(sk + (size_t)row * N_FFT);
    #pragma unroll 4
    for (int it = 0; it < N_FFT / 128; ++it) {          // 125 iterations
        int idx4 = it * 32 + lane;
        float4 v = p[idx4];
        int base = idx4 * 4;
        if (v.x != 0.f) { H[row] = base;     S[row] = v.x; }
        if (v.y != 0.f) { H[row] = base + 1; S[row] = v.y; }
        if (v.z != 0.f) { H[row] = base + 2; S[row] = v.z; }
        if (v.w != 0.f) { H[row] = base + 3; S[row] = v.w; }
    }
}

// ---------------- kernel 2: TWO batch rows per CTA (R13 code + 1-line fused partial) ----------------
__global__ __launch_bounds__(TPB, 1)
void cbp_main(const float* __restrict__ x1, const float* __restrict__ x2,
              float* __restrict__ out) {
    extern __shared__ __align__(16) unsigned char smraw[];
    float2* buf = (float2*)smraw;                              // 16000 complex
    float2* w   = (float2*)(smraw + N_FFT * sizeof(float2));   // 8000 twiddles
    const int tid = threadIdx.x;
    const int b0  = 2 * blockIdx.x;
    float2* park = g_park + (size_t)blockIdx.x * N_FFT;
    float*  part = g_part2 + (size_t)blockIdx.x * N_FFT;

    const float wstep = -6.283185307179586477f / (float)N_FFT;
    for (int k = tid; k < 8000; k += TPB) {
        float sn, cs;
        sincosf(wstep * (float)k, &sn, &cs);
        w[k] = make_float2(cs, sn);
    }

    // ---- row b0 ----
    scatter_row(buf, x1, x2, b0, tid);
    fft16000(buf, w, tid, false);
    spectral_product(buf, tid);
    #pragma unroll
    for (int q = 0; q < NQ; ++q) {          // park G_b0
        int p = tid + q * TPB;
        park[p] = buf[p];
    }
    // per-thread index sets of park-read/zero-write coincide -> no sync needed

    // ---- row b0+1 ----
    scatter_row(buf, x1, x2, b0 + 1, tid);
    fft16000(buf, w, tid, false);
    spectral_product(buf, tid);

    // combine: buf = G_b0 + i * G_{b0+1}
    #pragma unroll
    for (int q = 0; q < NQ; ++q) {
        int p = tid + q * TPB;
        float2 g1 = park[p];
        float2 g2 = buf[p];
        buf[p] = make_float2(g1.x - g2.y, g1.y + g2.x);
    }
    __syncthreads();

    fft16000(buf, w, tid, true);            // unnormalized inverse = N * cbp

    // signed sqrt + fused per-column ss^2 partial (ss^2 = |cbp| exactly)
    for (int k = tid; k < N_FFT; k += TPB) {
        float2 c = buf[k];
        out[(size_t)b0 * N_FFT + k]       = copysignf(sqrtf(fabsf(c.x)), c.x);
        out[(size_t)(b0 + 1) * N_FFT + k] = copysignf(sqrtf(fabsf(c.y)), c.y);
        part[k] = fabsf(c.x) + fabsf(c.y);
    }
}

// ---------------- kernel 3: finalize column norms (parallel deterministic reduce) ----------------
// grid = N_FFT/32 blocks x 256 threads; block owns 32 columns; 8 warps each sum
// a stride-8 subset of the 256 CTA partials (coalesced), then fixed-order combine.
__global__ void cbp_colsum_final() {
    __shared__ float red[8][32];
    int kk = threadIdx.x & 31;
    int cg = threadIdx.x >> 5;           // 0..7
    int k  = blockIdx.x * 32 + kk;
    float acc = 0.f;
    #pragma unroll 8
    for (int c = cg; c < NCTA; c += 8)
        acc += g_part2[(size_t)c * N_FFT + k];
    red[cg][kk] = acc;
    __syncthreads();
    if (cg == 0) {
        float s = 0.f;
        #pragma unroll
        for (int g = 0; g < 8; ++g) s += red[g][kk];
        g_norminv[k] = 1.f / fmaxf(sqrtf(s), 1e-12f);
    }
}

// ---------------- kernel 4: scale output columns ----------------
__global__ void cbp_norm(float* __restrict__ out) {
    int i = blockIdx.x * blockDim.x + threadIdx.x;
    if (i >= BATCH * N_FFT / 4) return;
    int e = i * 4;
    int k = e % N_FFT;
    float4 v = ((float4*)out)[i];
    v.x *= g_norminv[k];
    v.y *= g_norminv[k + 1];
    v.z *= g_norminv[k + 2];
    v.w *= g_norminv[k + 3];
    ((float4*)out)[i] = v;
}

// ---------------- launch ----------------
extern "C" void kernel_launch(void* const* d_in, const int* in_sizes, int n_in,
                              void* d_out, int out_size) {
    const float* xs[2]  = {nullptr, nullptr};
    const float* sks[2] = {nullptr, nullptr};
    int nx = 0, ns = 0;
    for (int i = 0; i < n_in; ++i) {
        if (in_sizes[i] == BATCH * IN_DIM && nx < 2)       xs[nx++]  = (const float*)d_in[i];
        else if (in_sizes[i] == IN_DIM * N_FFT && ns < 2)  sks[ns++] = (const float*)d_in[i];
    }
    float* out = (float*)d_out;

    cudaFuncSetAttribute(cbp_main, cudaFuncAttributeMaxDynamicSharedMemorySize, SMEM_BYTES);

    cbp_extract<<<(2 * IN_DIM * 32 + 255) / 256, 256>>>(sks[0], sks[1]);
    cbp_main<<<NCTA, TPB, SMEM_BYTES>>>(xs[0], xs[1], out);
    cbp_colsum_final<<<N_FFT / 32, 256>>>();
    cbp_norm<<<(BATCH * N_FFT / 4 + 255) / 256, 256>>>(out);
}